// round 14
// baseline (speedup 1.0000x reference)
#include <cuda_runtime.h>
#include <cuda_fp16.h>
#include <math.h>
#include <stdint.h>

#define BATCH 512
#define NFEAT 128
#define NTRIP 1024
#define NGRAM 256            // gram blocks (2 antithetic a-values each)
#define NPAIR 8128
#define VS2 136              // word stride per colpair row (feat dim + 8 pad)

// ---------------- device scratch ---------------------------------------------
__device__ float g_m[BATCH * NFEAT];
__device__ float g_mp[64][NFEAT];                // per-block colsum partials of m
__device__ float g_part[NGRAM * NFEAT * NFEAT];  // split-K partials (upper tiles)
__device__ float g_S[NFEAT * NFEAT];             // final S'/2 (upper valid)
__device__ float g_tpart[2];                     // triplet partials

__device__ __forceinline__ void mma_f16(float* d, const uint32_t* a,
                                        uint32_t b0, uint32_t b1) {
    asm volatile(
        "mma.sync.aligned.m16n8k16.row.col.f32.f16.f16.f32 "
        "{%0,%1,%2,%3}, {%4,%5,%6,%7}, {%8,%9}, {%0,%1,%2,%3};"
        : "+f"(d[0]), "+f"(d[1]), "+f"(d[2]), "+f"(d[3])
        : "r"(a[0]), "r"(a[1]), "r"(a[2]), "r"(a[3]), "r"(b0), "r"(b1));
}

// ---- K1: fused pre-pass -----------------------------------------------------
// blocks 0-63:  row means (8 a-values each) + column-sum partials of m
// blocks 64-65: triplet loss (512 triplets each)
__global__ void __launch_bounds__(512) k_pre(const float* __restrict__ emb,
                                             const int* __restrict__ trip32) {
    __shared__ float s_red[4][8][NFEAT];   // 16 KB, reused by both paths
    int bid = blockIdx.x;
    int tid = threadIdx.x;

    if (bid < 64) {
        int f = tid & 127, h = tid >> 7;
        int a0 = bid * 8;
        float xa[8];
#pragma unroll
        for (int aa = 0; aa < 8; aa++) xa[aa] = emb[(a0 + aa) * NFEAT + f];
        float s[8];
#pragma unroll
        for (int aa = 0; aa < 8; aa++) s[aa] = 0.f;
        int bbase = h * 128;
        for (int b0 = 0; b0 < 128; b0 += 4) {
            float v[4];
#pragma unroll
            for (int u = 0; u < 4; u++) v[u] = emb[(bbase + b0 + u) * NFEAT + f];
#pragma unroll
            for (int u = 0; u < 4; u++)
#pragma unroll
                for (int aa = 0; aa < 8; aa++) s[aa] += fabsf(xa[aa] - v[u]);
        }
#pragma unroll
        for (int aa = 0; aa < 8; aa++) s_red[h][aa][f] = s[aa];
        __syncthreads();
        if (h == 0) {
            float csum = 0.f;
#pragma unroll
            for (int aa = 0; aa < 8; aa++) {
                float t = s_red[0][aa][f] + s_red[1][aa][f] +
                          s_red[2][aa][f] + s_red[3][aa][f];
                t *= (1.f / BATCH);
                g_m[(a0 + aa) * NFEAT + f] = t;
                csum += t;
            }
            g_mp[bid][f] = csum;
        }
        return;
    }

    // ---- triplet path (blocks 64,65) ----
    float* red = &s_red[0][0][0];   // 512 floats
    bool is64 = (trip32[1] == 0) && (trip32[3] == 0) &&
                (trip32[5] == 0) && (trip32[7] == 0) &&
                ((trip32[0] | trip32[2] | trip32[4] | trip32[6]) != 0);
    int t = (bid - 64) * 512 + tid;
    float s = 0.f;
    if (t < NTRIP) {
        int p, q, r;
        if (is64) {
            p = trip32[(3 * t + 0) * 2];
            q = trip32[(3 * t + 1) * 2];
            r = trip32[(3 * t + 2) * 2];
        } else {
            p = trip32[3 * t + 0];
            q = trip32[3 * t + 1];
            r = trip32[3 * t + 2];
        }
        const float* pp = &emb[p * NFEAT];
        const float* pq = &emb[q * NFEAT];
        const float* pr = &emb[r * NFEAT];
        float ap = 0.f, an = 0.f;
#pragma unroll 8
        for (int f = 0; f < NFEAT; f++) {
            float pv = pp[f];
            float d1 = pv - pq[f]; ap += d1 * d1;
            float d2 = pv - pr[f]; an += d2 * d2;
        }
        float lv = ap - an + 1.0f;
        s = (lv > 0.f) ? lv : 0.f;
    }
    red[tid] = s;
    __syncthreads();
    for (int o = 256; o > 0; o >>= 1) {
        if (tid < o) red[tid] += red[tid + o];
        __syncthreads();
    }
    if (tid == 0) g_tpart[bid - 64] = red[0];
}

// ---- K2: fp16 m16n8k16 Gram, upper-triangle tiles, double-buffered ----------
// s_v word [cp][f] = half2( |x_a-x_{b0}|[f], |x_a-x_{b1}|[f] ), b0=2cp, b1=2cp+1.
// Warp tile map covering i<=j:
//  w0: r0-31 c0-63 (nu=8)  w1: r32-63 c32-63 (nu=4)  w2: r0-31 c64-127 (nu=8)
//  w3: r32-63 c64-127      w4: r64-95 c64-127        w5: r96-127 c64-127
//  w6,w7: gen-only
__global__ void __launch_bounds__(256, 2) k_gram(const float* __restrict__ emb) {
    __shared__ __align__(16) uint32_t s_v[2][16][VS2];
    __shared__ float s_m[2][NFEAT];

    const int blk = blockIdx.x;
    const int tid = threadIdx.x;
    const int lane = tid & 31;
    const int w = tid >> 5;

    const int rb_t[8] = {0, 32, 0, 32, 64, 96, 0, 0};
    const int cb_t[8] = {0, 32, 64, 64, 64, 64, 0, 0};
    const int nu_t[8] = {8, 4, 8, 8, 8, 8, 0, 0};
    const int rbase = rb_t[w], cbase = cb_t[w], nu = nu_t[w];

    const int cp = lane & 15;
    const int fh = lane >> 4;
    const int fbase = w * 16 + fh * 8;

    float d[2][8][4];
#pragma unroll
    for (int rt = 0; rt < 2; rt++)
#pragma unroll
        for (int j = 0; j < 8; j++)
#pragma unroll
            for (int e = 0; e < 4; e++) d[rt][j][e] = 0.f;

    int alist[2] = {blk, 511 - blk};
    int tcnt = 0;

    for (int ai = 0; ai < 2; ai++) {
        const int a = alist[ai];
        const int nb = 511 - a;
        if (nb <= 0) continue;

        float xaf[8];
        {
            float4 t0 = *(const float4*)&emb[a * NFEAT + fbase];
            float4 t1 = *(const float4*)&emb[a * NFEAT + fbase + 4];
            xaf[0] = t0.x; xaf[1] = t0.y; xaf[2] = t0.z; xaf[3] = t0.w;
            xaf[4] = t1.x; xaf[5] = t1.y; xaf[6] = t1.z; xaf[7] = t1.w;
        }

        const int ntile = (nb + 31) >> 5;
        int b0 = a + 1 + 2 * cp, b1 = b0 + 1;
        bool ok0 = (b0 < BATCH), ok1 = (b1 < BATCH);
        float fA[8], fB[8];
        {
            const float4* sA = (const float4*)&emb[(ok0 ? b0 : (BATCH - 1)) * NFEAT + fbase];
            const float4* sB = (const float4*)&emb[(ok1 ? b1 : (BATCH - 1)) * NFEAT + fbase];
            float4 a0v = sA[0], a1v = sA[1], b0v = sB[0], b1v = sB[1];
            fA[0] = a0v.x; fA[1] = a0v.y; fA[2] = a0v.z; fA[3] = a0v.w;
            fA[4] = a1v.x; fA[5] = a1v.y; fA[6] = a1v.z; fA[7] = a1v.w;
            fB[0] = b0v.x; fB[1] = b0v.y; fB[2] = b0v.z; fB[3] = b0v.w;
            fB[4] = b1v.x; fB[5] = b1v.y; fB[6] = b1v.z; fB[7] = b1v.w;
        }

        for (int t = 0; t < ntile; t++, tcnt++) {
            const int buf = tcnt & 1;
            uint32_t hw[8];
#pragma unroll
            for (int e = 0; e < 8; e++) {
                float v0 = ok0 ? fabsf(xaf[e] - fA[e]) : 0.f;
                float v1 = ok1 ? fabsf(xaf[e] - fB[e]) : 0.f;
                __half2 h2 = __floats2half2_rn(v0, v1);
                hw[e] = *(uint32_t*)&h2;
            }
            *(uint4*)&s_v[buf][cp][fbase] =
                make_uint4(hw[0], hw[1], hw[2], hw[3]);
            *(uint4*)&s_v[buf][cp][fbase + 4] =
                make_uint4(hw[4], hw[5], hw[6], hw[7]);
            __syncthreads();

            if (t + 1 < ntile) {
                b0 = a + 1 + (t + 1) * 32 + 2 * cp;
                b1 = b0 + 1;
                ok0 = (b0 < BATCH);
                ok1 = (b1 < BATCH);
                const float4* sA = (const float4*)&emb[(ok0 ? b0 : (BATCH - 1)) * NFEAT + fbase];
                const float4* sB = (const float4*)&emb[(ok1 ? b1 : (BATCH - 1)) * NFEAT + fbase];
                float4 a0v = sA[0], a1v = sA[1], b0v = sB[0], b1v = sB[1];
                fA[0] = a0v.x; fA[1] = a0v.y; fA[2] = a0v.z; fA[3] = a0v.w;
                fA[4] = a1v.x; fA[5] = a1v.y; fA[6] = a1v.z; fA[7] = a1v.w;
                fB[0] = b0v.x; fB[1] = b0v.y; fB[2] = b0v.z; fB[3] = b0v.w;
                fB[4] = b1v.x; fB[5] = b1v.y; fB[6] = b1v.z; fB[7] = b1v.w;
            }

            if (nu > 0) {
#pragma unroll
                for (int ks = 0; ks < 2; ks++) {
                    const int k0 = ks * 8 + (lane & 3);
                    const int ar = lane >> 2;
                    uint32_t afr[2][4];
#pragma unroll
                    for (int rt = 0; rt < 2; rt++) {
                        int r = rbase + rt * 16 + ar;
                        afr[rt][0] = s_v[buf][k0][r];
                        afr[rt][1] = s_v[buf][k0][r + 8];
                        afr[rt][2] = s_v[buf][k0 + 4][r];
                        afr[rt][3] = s_v[buf][k0 + 4][r + 8];
                    }
#pragma unroll
                    for (int j = 0; j < 8; j++) {
                        if (j < nu) {
                            int n = cbase + j * 8 + ar;
                            uint32_t bf0 = s_v[buf][k0][n];
                            uint32_t bf1 = s_v[buf][k0 + 4][n];
                            mma_f16(d[0][j], afr[0], bf0, bf1);
                            mma_f16(d[1][j], afr[1], bf0, bf1);
                        }
                    }
                }
            }
        }
    }

    // ---- fp32 epilogue: -B * sum_{a in blk} m_a m_a^T (warp tiles only) -----
    __syncthreads();
    {
        int aa = tid >> 7, f = tid & 127;
        s_m[aa][f] = g_m[alist[aa] * NFEAT + f];
    }
    __syncthreads();

    const int gr = lane >> 2, gc = (lane & 3) * 2;
    const float Bf = (float)BATCH;
    if (nu > 0) {
#pragma unroll
        for (int aa = 0; aa < 2; aa++) {
            float am[4];
#pragma unroll
            for (int rt = 0; rt < 2; rt++) {
                am[rt * 2 + 0] = s_m[aa][rbase + rt * 16 + gr];
                am[rt * 2 + 1] = s_m[aa][rbase + rt * 16 + gr + 8];
            }
#pragma unroll
            for (int j = 0; j < 8; j++) {
                if (j < nu) {
                    float bm0 = s_m[aa][cbase + j * 8 + gc];
                    float bm1 = s_m[aa][cbase + j * 8 + gc + 1];
#pragma unroll
                    for (int rt = 0; rt < 2; rt++) {
                        d[rt][j][0] -= Bf * am[rt * 2 + 0] * bm0;
                        d[rt][j][1] -= Bf * am[rt * 2 + 0] * bm1;
                        d[rt][j][2] -= Bf * am[rt * 2 + 1] * bm0;
                        d[rt][j][3] -= Bf * am[rt * 2 + 1] * bm1;
                    }
                }
            }
        }

        float* out = &g_part[blk * NFEAT * NFEAT];
#pragma unroll
        for (int rt = 0; rt < 2; rt++)
#pragma unroll
            for (int j = 0; j < 8; j++) {
                if (j < nu) {
                    int row = rbase + rt * 16 + gr;
                    int col = cbase + j * 8 + gc;
                    out[row * NFEAT + col] = d[rt][j][0];
                    out[row * NFEAT + col + 1] = d[rt][j][1];
                    out[(row + 8) * NFEAT + col] = d[rt][j][2];
                    out[(row + 8) * NFEAT + col + 1] = d[rt][j][3];
                }
            }
    }
}

// ---- K3: fused reduction: sum 256 slabs + 0.5*Msum Msum^T (upper only) ------
__global__ void __launch_bounds__(256) k_reduce(const float* __restrict__ emb) {
    int idx = blockIdx.x * blockDim.x + threadIdx.x;  // 0..16383
    int i = idx >> 7, j = idx & 127;
    float s = 0.f;
    if (j >= i) {
#pragma unroll 8
        for (int k = 0; k < NGRAM; k++)
            s += g_part[k * NFEAT * NFEAT + idx];
        float mi = 0.f, mj = 0.f;
#pragma unroll
        for (int p = 0; p < 64; p++) {
            mi += g_mp[p][i];
            mj += g_mp[p][j];
        }
        s += 0.5f * mi * mj;
    }
    g_S[idx] = s;
    (void)emb;
}

// ---- K4: epilogue (reads only i<=j entries of g_S) --------------------------
__global__ void k_final(const float* __restrict__ emb, float* __restrict__ out) {
    __shared__ float q[NFEAT];
    __shared__ float red[256];
    int tid = threadIdx.x;
    if (tid < NFEAT)
        q[tid] = sqrtf(sqrtf(fmaxf(2.f * g_S[tid * NFEAT + tid], 0.f)));
    __syncthreads();

    float s = 0.f;
    int p0 = tid * 32;
    if (p0 < NPAIR) {
        float disc = 65025.f - 8.f * (float)p0;
        int i = (int)((255.f - sqrtf(disc)) * 0.5f);
        if (i < 0) i = 0;
        while (i > 0 && (127 * i - (i * (i - 1)) / 2) > p0) i--;
        while ((127 * (i + 1) - ((i + 1) * i) / 2) <= p0) i++;
        int j = i + 1 + (p0 - (127 * i - (i * (i - 1)) / 2));
        int pend = p0 + 32;
        if (pend > NPAIR) pend = NPAIR;
        for (int p = p0; p < pend; p++) {
            float sij = 2.f * g_S[i * NFEAT + j];
            s += sqrtf(fmaxf(sij, 0.f)) / (q[i] * q[j]);
            if (++j >= NFEAT) { i++; j = i + 1; }
        }
    }
    red[tid] = s;
    __syncthreads();
    for (int o = 128; o > 0; o >>= 1) {
        if (tid < o) red[tid] += red[tid + o];
        __syncthreads();
    }
    if (tid == 0)
        out[0] = (g_tpart[0] + g_tpart[1]) * (1.f / NTRIP) + red[0] * (1.f / NPAIR);
    (void)emb;
}

// ---- launch: 4 kernels ------------------------------------------------------
extern "C" void kernel_launch(void* const* d_in, const int* in_sizes, int n_in,
                              void* d_out, int out_size) {
    const float* emb = (const float*)d_in[0];
    const int* trip = (const int*)d_in[1];
    float* out = (float*)d_out;

    k_pre<<<66, 512>>>(emb, trip);
    k_gram<<<NGRAM, 256>>>(emb);
    k_reduce<<<64, 256>>>(emb);
    k_final<<<1, 256>>>(emb, out);
}

// round 15
// speedup vs baseline: 1.3949x; 1.3949x over previous
#include <cuda_runtime.h>
#include <cuda_fp16.h>
#include <math.h>
#include <stdint.h>

#define BATCH 512
#define NFEAT 128
#define NTRIP 1024
#define NGRAM 256            // gram blocks (2 antithetic a-values each)
#define NTBLK 4
#define NPAIR 8128
#define VS2 136              // word stride per colpair row (feat dim + 8 pad)
#define NRED1 16             // stage-1 reduction slices

// ---------------- device scratch ---------------------------------------------
__device__ float g_m[BATCH * NFEAT];
__device__ float g_mp[64][NFEAT];                // per-block colsum partials of m
__device__ float g_part[NGRAM * NFEAT * NFEAT];  // split-K partials (upper tiles)
__device__ float g_Sr[NRED1 * NFEAT * NFEAT];    // stage-1 sums (upper)
__device__ float g_S[NFEAT * NFEAT];             // final S'/2 (upper valid)
__device__ float g_tpart[NTBLK];

__device__ __forceinline__ void mma_f16(float* d, const uint32_t* a,
                                        uint32_t b0, uint32_t b1) {
    asm volatile(
        "mma.sync.aligned.m16n8k16.row.col.f32.f16.f16.f32 "
        "{%0,%1,%2,%3}, {%4,%5,%6,%7}, {%8,%9}, {%0,%1,%2,%3};"
        : "+f"(d[0]), "+f"(d[1]), "+f"(d[2]), "+f"(d[3])
        : "r"(a[0]), "r"(a[1]), "r"(a[2]), "r"(a[3]), "r"(b0), "r"(b1));
}

// ---- K1: row means + colsum partials; 64 blocks x 8 a-values ---------------
__global__ void __launch_bounds__(512) k_means(const float* __restrict__ emb) {
    __shared__ float s_red[4][8][NFEAT];
    int tid = threadIdx.x;
    int f = tid & 127, h = tid >> 7;
    int a0 = blockIdx.x * 8;
    float xa[8];
#pragma unroll
    for (int aa = 0; aa < 8; aa++) xa[aa] = emb[(a0 + aa) * NFEAT + f];
    float s[8];
#pragma unroll
    for (int aa = 0; aa < 8; aa++) s[aa] = 0.f;
    int bbase = h * 128;
    for (int b0 = 0; b0 < 128; b0 += 4) {
        float v[4];
#pragma unroll
        for (int u = 0; u < 4; u++) v[u] = emb[(bbase + b0 + u) * NFEAT + f];
#pragma unroll
        for (int u = 0; u < 4; u++)
#pragma unroll
            for (int aa = 0; aa < 8; aa++) s[aa] += fabsf(xa[aa] - v[u]);
    }
#pragma unroll
    for (int aa = 0; aa < 8; aa++) s_red[h][aa][f] = s[aa];
    __syncthreads();
    if (h == 0) {
        float csum = 0.f;
#pragma unroll
        for (int aa = 0; aa < 8; aa++) {
            float t = s_red[0][aa][f] + s_red[1][aa][f] +
                      s_red[2][aa][f] + s_red[3][aa][f];
            t *= (1.f / BATCH);
            g_m[(a0 + aa) * NFEAT + f] = t;
            csum += t;
        }
        g_mp[blockIdx.x][f] = csum;
    }
}

// ---- K2: triplet loss partials ----------------------------------------------
__global__ void k_triplet(const float* __restrict__ emb,
                          const int* __restrict__ trip32) {
    __shared__ float red[256];
    int tid = threadIdx.x;
    bool is64 = (trip32[1] == 0) && (trip32[3] == 0) &&
                (trip32[5] == 0) && (trip32[7] == 0) &&
                ((trip32[0] | trip32[2] | trip32[4] | trip32[6]) != 0);
    int t = blockIdx.x * 256 + tid;
    float s = 0.f;
    if (t < NTRIP) {
        int p, q, r;
        if (is64) {
            p = trip32[(3 * t + 0) * 2];
            q = trip32[(3 * t + 1) * 2];
            r = trip32[(3 * t + 2) * 2];
        } else {
            p = trip32[3 * t + 0];
            q = trip32[3 * t + 1];
            r = trip32[3 * t + 2];
        }
        const float* pp = &emb[p * NFEAT];
        const float* pq = &emb[q * NFEAT];
        const float* pr = &emb[r * NFEAT];
        float ap = 0.f, an = 0.f;
#pragma unroll 8
        for (int f = 0; f < NFEAT; f++) {
            float pv = pp[f];
            float d1 = pv - pq[f]; ap += d1 * d1;
            float d2 = pv - pr[f]; an += d2 * d2;
        }
        float lv = ap - an + 1.0f;
        s = (lv > 0.f) ? lv : 0.f;
    }
    red[tid] = s;
    __syncthreads();
    for (int o = 128; o > 0; o >>= 1) {
        if (tid < o) red[tid] += red[tid + o];
        __syncthreads();
    }
    if (tid == 0) g_tpart[blockIdx.x] = red[0];
}

// ---- K3: fp16 m16n8k16 Gram, upper-triangle tiles, double-buffered ----------
__global__ void __launch_bounds__(256, 2) k_gram(const float* __restrict__ emb) {
    __shared__ __align__(16) uint32_t s_v[2][16][VS2];
    __shared__ float s_m[2][NFEAT];

    const int blk = blockIdx.x;
    const int tid = threadIdx.x;
    const int lane = tid & 31;
    const int w = tid >> 5;

    const int rb_t[8] = {0, 32, 0, 32, 64, 96, 0, 0};
    const int cb_t[8] = {0, 32, 64, 64, 64, 64, 0, 0};
    const int nu_t[8] = {8, 4, 8, 8, 8, 8, 0, 0};
    const int rbase = rb_t[w], cbase = cb_t[w], nu = nu_t[w];

    const int cp = lane & 15;
    const int fh = lane >> 4;
    const int fbase = w * 16 + fh * 8;

    float d[2][8][4];
#pragma unroll
    for (int rt = 0; rt < 2; rt++)
#pragma unroll
        for (int j = 0; j < 8; j++)
#pragma unroll
            for (int e = 0; e < 4; e++) d[rt][j][e] = 0.f;

    int alist[2] = {blk, 511 - blk};
    int tcnt = 0;

    for (int ai = 0; ai < 2; ai++) {
        const int a = alist[ai];
        const int nb = 511 - a;
        if (nb <= 0) continue;

        float xaf[8];
        {
            float4 t0 = *(const float4*)&emb[a * NFEAT + fbase];
            float4 t1 = *(const float4*)&emb[a * NFEAT + fbase + 4];
            xaf[0] = t0.x; xaf[1] = t0.y; xaf[2] = t0.z; xaf[3] = t0.w;
            xaf[4] = t1.x; xaf[5] = t1.y; xaf[6] = t1.z; xaf[7] = t1.w;
        }

        const int ntile = (nb + 31) >> 5;
        int b0 = a + 1 + 2 * cp, b1 = b0 + 1;
        bool ok0 = (b0 < BATCH), ok1 = (b1 < BATCH);
        float fA[8], fB[8];
        {
            const float4* sA = (const float4*)&emb[(ok0 ? b0 : (BATCH - 1)) * NFEAT + fbase];
            const float4* sB = (const float4*)&emb[(ok1 ? b1 : (BATCH - 1)) * NFEAT + fbase];
            float4 a0v = sA[0], a1v = sA[1], b0v = sB[0], b1v = sB[1];
            fA[0] = a0v.x; fA[1] = a0v.y; fA[2] = a0v.z; fA[3] = a0v.w;
            fA[4] = a1v.x; fA[5] = a1v.y; fA[6] = a1v.z; fA[7] = a1v.w;
            fB[0] = b0v.x; fB[1] = b0v.y; fB[2] = b0v.z; fB[3] = b0v.w;
            fB[4] = b1v.x; fB[5] = b1v.y; fB[6] = b1v.z; fB[7] = b1v.w;
        }

        for (int t = 0; t < ntile; t++, tcnt++) {
            const int buf = tcnt & 1;
            uint32_t hw[8];
#pragma unroll
            for (int e = 0; e < 8; e++) {
                float v0 = ok0 ? fabsf(xaf[e] - fA[e]) : 0.f;
                float v1 = ok1 ? fabsf(xaf[e] - fB[e]) : 0.f;
                __half2 h2 = __floats2half2_rn(v0, v1);
                hw[e] = *(uint32_t*)&h2;
            }
            *(uint4*)&s_v[buf][cp][fbase] =
                make_uint4(hw[0], hw[1], hw[2], hw[3]);
            *(uint4*)&s_v[buf][cp][fbase + 4] =
                make_uint4(hw[4], hw[5], hw[6], hw[7]);
            __syncthreads();

            if (t + 1 < ntile) {
                b0 = a + 1 + (t + 1) * 32 + 2 * cp;
                b1 = b0 + 1;
                ok0 = (b0 < BATCH);
                ok1 = (b1 < BATCH);
                const float4* sA = (const float4*)&emb[(ok0 ? b0 : (BATCH - 1)) * NFEAT + fbase];
                const float4* sB = (const float4*)&emb[(ok1 ? b1 : (BATCH - 1)) * NFEAT + fbase];
                float4 a0v = sA[0], a1v = sA[1], b0v = sB[0], b1v = sB[1];
                fA[0] = a0v.x; fA[1] = a0v.y; fA[2] = a0v.z; fA[3] = a0v.w;
                fA[4] = a1v.x; fA[5] = a1v.y; fA[6] = a1v.z; fA[7] = a1v.w;
                fB[0] = b0v.x; fB[1] = b0v.y; fB[2] = b0v.z; fB[3] = b0v.w;
                fB[4] = b1v.x; fB[5] = b1v.y; fB[6] = b1v.z; fB[7] = b1v.w;
            }

            if (nu > 0) {
#pragma unroll
                for (int ks = 0; ks < 2; ks++) {
                    const int k0 = ks * 8 + (lane & 3);
                    const int ar = lane >> 2;
                    uint32_t afr[2][4];
#pragma unroll
                    for (int rt = 0; rt < 2; rt++) {
                        int r = rbase + rt * 16 + ar;
                        afr[rt][0] = s_v[buf][k0][r];
                        afr[rt][1] = s_v[buf][k0][r + 8];
                        afr[rt][2] = s_v[buf][k0 + 4][r];
                        afr[rt][3] = s_v[buf][k0 + 4][r + 8];
                    }
#pragma unroll
                    for (int j = 0; j < 8; j++) {
                        if (j < nu) {
                            int n = cbase + j * 8 + ar;
                            uint32_t bf0 = s_v[buf][k0][n];
                            uint32_t bf1 = s_v[buf][k0 + 4][n];
                            mma_f16(d[0][j], afr[0], bf0, bf1);
                            mma_f16(d[1][j], afr[1], bf0, bf1);
                        }
                    }
                }
            }
        }
    }

    // ---- fp32 epilogue: -B * sum_{a in blk} m_a m_a^T -----------------------
    __syncthreads();
    {
        int aa = tid >> 7, f = tid & 127;
        s_m[aa][f] = g_m[alist[aa] * NFEAT + f];
    }
    __syncthreads();

    const int gr = lane >> 2, gc = (lane & 3) * 2;
    const float Bf = (float)BATCH;
    if (nu > 0) {
#pragma unroll
        for (int aa = 0; aa < 2; aa++) {
            float am[4];
#pragma unroll
            for (int rt = 0; rt < 2; rt++) {
                am[rt * 2 + 0] = s_m[aa][rbase + rt * 16 + gr];
                am[rt * 2 + 1] = s_m[aa][rbase + rt * 16 + gr + 8];
            }
#pragma unroll
            for (int j = 0; j < 8; j++) {
                if (j < nu) {
                    float bm0 = s_m[aa][cbase + j * 8 + gc];
                    float bm1 = s_m[aa][cbase + j * 8 + gc + 1];
#pragma unroll
                    for (int rt = 0; rt < 2; rt++) {
                        d[rt][j][0] -= Bf * am[rt * 2 + 0] * bm0;
                        d[rt][j][1] -= Bf * am[rt * 2 + 0] * bm1;
                        d[rt][j][2] -= Bf * am[rt * 2 + 1] * bm0;
                        d[rt][j][3] -= Bf * am[rt * 2 + 1] * bm1;
                    }
                }
            }
        }

        float* out = &g_part[blk * NFEAT * NFEAT];
#pragma unroll
        for (int rt = 0; rt < 2; rt++)
#pragma unroll
            for (int j = 0; j < 8; j++) {
                if (j < nu) {
                    int row = rbase + rt * 16 + gr;
                    int col = cbase + j * 8 + gc;
                    out[row * NFEAT + col] = d[rt][j][0];
                    out[row * NFEAT + col + 1] = d[rt][j][1];
                    out[(row + 8) * NFEAT + col] = d[rt][j][2];
                    out[(row + 8) * NFEAT + col + 1] = d[rt][j][3];
                }
            }
    }
}

// ---- K4a: reduction stage 1, upper triangle only (1024 blocks) --------------
__global__ void k_reduce1(const float* __restrict__ emb) {
    int idx = blockIdx.x * blockDim.x + threadIdx.x;  // 0..16383
    int ks = blockIdx.y;                              // 0..15
    int i = idx >> 7, j = idx & 127;
    float s = 0.f;
    if (j >= i) {
#pragma unroll
        for (int k = ks * 16; k < ks * 16 + 16; k++)
            s += g_part[k * NFEAT * NFEAT + idx];
    }
    g_Sr[ks * NFEAT * NFEAT + idx] = s;
    (void)emb;
}

// ---- K4b: reduction stage 2 + 0.5*Msum Msum^T (upper only) ------------------
__global__ void k_reduce2(const float* __restrict__ emb) {
    int idx = blockIdx.x * blockDim.x + threadIdx.x;
    int i = idx >> 7, j = idx & 127;
    float s = 0.f;
    if (j >= i) {
#pragma unroll
        for (int k = 0; k < NRED1; k++)
            s += g_Sr[k * NFEAT * NFEAT + idx];
        float mi = 0.f, mj = 0.f;
#pragma unroll
        for (int p = 0; p < 64; p++) {
            mi += g_mp[p][i];
            mj += g_mp[p][j];
        }
        s += 0.5f * mi * mj;
    }
    g_S[idx] = s;
    (void)emb;
}

// ---- K5: epilogue; fixed 32-iter unrolled loop -> batched LDGs --------------
__global__ void k_final(const float* __restrict__ emb, float* __restrict__ out) {
    __shared__ float qinv[NFEAT];
    __shared__ float red[256];
    int tid = threadIdx.x;
    if (tid < NFEAT) {
        float qv = sqrtf(sqrtf(fmaxf(2.f * g_S[tid * NFEAT + tid], 0.f)));
        qinv[tid] = 1.f / qv;
    }
    __syncthreads();

    float s = 0.f;
    int p0 = tid * 32;
    if (p0 < NPAIR) {   // threads 0..253 each own exactly 32 pairs
        float disc = 65025.f - 8.f * (float)p0;
        int i = (int)((255.f - sqrtf(disc)) * 0.5f);
        if (i < 0) i = 0;
        while (i > 0 && (127 * i - (i * (i - 1)) / 2) > p0) i--;
        while ((127 * (i + 1) - ((i + 1) * i) / 2) <= p0) i++;
        int j = i + 1 + (p0 - (127 * i - (i * (i - 1)) / 2));
#pragma unroll
        for (int u = 0; u < 32; u++) {
            float sij = 2.f * g_S[i * NFEAT + j];
            s += sqrtf(fmaxf(sij, 0.f)) * qinv[i] * qinv[j];
            if (++j >= NFEAT) { i++; j = i + 1; }
        }
    }
    red[tid] = s;
    __syncthreads();
    for (int o = 128; o > 0; o >>= 1) {
        if (tid < o) red[tid] += red[tid + o];
        __syncthreads();
    }
    if (tid == 0) {
        float tl = 0.f;
        for (int k = 0; k < NTBLK; k++) tl += g_tpart[k];
        out[0] = tl * (1.f / NTRIP) + red[0] * (1.f / NPAIR);
    }
    (void)emb;
}

// ---- launch: 6 kernels (reduce1 4th for ncu) --------------------------------
extern "C" void kernel_launch(void* const* d_in, const int* in_sizes, int n_in,
                              void* d_out, int out_size) {
    const float* emb = (const float*)d_in[0];
    const int* trip = (const int*)d_in[1];
    float* out = (float*)d_out;

    k_means<<<64, 512>>>(emb);
    k_triplet<<<NTBLK, 256>>>(emb, trip);
    k_gram<<<NGRAM, 256>>>(emb);
    dim3 r1(64, NRED1);
    k_reduce1<<<r1, 256>>>(emb);
    k_reduce2<<<64, 256>>>(emb);
    k_final<<<1, 256>>>(emb, out);
}